// round 17
// baseline (speedup 1.0000x reference)
#include <cuda_runtime.h>
#include <cuda_fp16.h>
#include <math.h>
#include <stdint.h>

#define BB   8
#define SS   256
#define HH   768
#define NLL  12
#define NHH  12
#define FFF  3072
#define CC   9
#define DHH  64
#define TOK  (BB*SS)   // 2048

// ================= scratch =================
__device__ float                  g_h    [TOK*HH];
__device__ __align__(256) __half  g_h16  [TOK*HH];
__device__ __align__(256) __half  g_qkv16[3*TOK*HH];
__device__ __align__(256) __half  g_cx16 [TOK*HH];
__device__ __align__(256) float   g_t1   [TOK*HH];
__device__ __align__(256) __half  g_f16  [TOK*FFF];
__device__ float                  g_em   [TOK*CC];

// fp16 weights in NATIVE [K][N] layout
__device__ __align__(256) __half w_qkv16[NLL*3*HH*HH];
__device__ __align__(256) __half w_ao16 [NLL*HH*HH];
__device__ __align__(256) __half w_f116 [NLL*HH*FFF];
__device__ __align__(256) __half w_f216 [NLL*FFF*HH];

// ================= low-level helpers =================
__device__ __forceinline__ void cpa16(uint32_t dst, const void* src) {
    asm volatile("cp.async.cg.shared.global [%0], [%1], 16;"
                 :: "r"(dst), "l"(src) : "memory");
}
#define CP_COMMIT() asm volatile("cp.async.commit_group;" ::: "memory")
#define CP_WAIT1()  asm volatile("cp.async.wait_group 1;" ::: "memory")
#define CP_WAIT0()  asm volatile("cp.async.wait_group 0;" ::: "memory")

__device__ __forceinline__ void ldm_x4(uint32_t* r, uint32_t a) {
    asm volatile("ldmatrix.sync.aligned.m8n8.x4.shared.b16 {%0,%1,%2,%3}, [%4];"
                 : "=r"(r[0]), "=r"(r[1]), "=r"(r[2]), "=r"(r[3]) : "r"(a));
}
__device__ __forceinline__ void ldm_x4_t(uint32_t* r, uint32_t a) {
    asm volatile("ldmatrix.sync.aligned.m8n8.x4.trans.shared.b16 {%0,%1,%2,%3}, [%4];"
                 : "=r"(r[0]), "=r"(r[1]), "=r"(r[2]), "=r"(r[3]) : "r"(a));
}
__device__ __forceinline__ void mma16816(float* c, const uint32_t* a, const uint32_t* b) {
    asm volatile("mma.sync.aligned.m16n8k16.row.col.f32.f16.f16.f32 "
        "{%0,%1,%2,%3}, {%4,%5,%6,%7}, {%8,%9}, {%0,%1,%2,%3};"
        : "+f"(c[0]), "+f"(c[1]), "+f"(c[2]), "+f"(c[3])
        : "r"(a[0]), "r"(a[1]), "r"(a[2]), "r"(a[3]), "r"(b[0]), "r"(b[1]));
}

__device__ __forceinline__ float gelu_tanh(float v) {
    float c = 0.7978845608028654f * (v + 0.044715f * v * v * v);
    return 0.5f * v * (1.f + tanhf(c));
}

// ================= streaming fp32 -> fp16 weight convert =================
__global__ void k_wconv(const float* __restrict__ W,
                        __half* __restrict__ out, size_t n) {
    size_t i = ((size_t)blockIdx.x * 256 + threadIdx.x) * 8;
    if (i < n) {
        float4 a = *(const float4*)(W + i);
        float4 b = *(const float4*)(W + i + 4);
        __half2 p0 = __halves2half2(__float2half(a.x), __float2half(a.y));
        __half2 p1 = __halves2half2(__float2half(a.z), __float2half(a.w));
        __half2 p2 = __halves2half2(__float2half(b.x), __float2half(b.y));
        __half2 p3 = __halves2half2(__float2half(b.z), __float2half(b.w));
        uint4 o;
        o.x = *(uint32_t*)&p0; o.y = *(uint32_t*)&p1;
        o.z = *(uint32_t*)&p2; o.w = *(uint32_t*)&p3;
        *(uint4*)(out + i) = o;
    }
}

// ================= HMMA GEMM: KCH=64, trans-B, 3-stage, 2 CTAs/SM =================
#define PADK 72   // 64 + 8

template<int BN>
__global__ __launch_bounds__(256, 2)
void k_mma(const __half* __restrict__ A,
           const __half* __restrict__ B16,
           const float* __restrict__ bias,
           float* __restrict__ Cf,
           __half* __restrict__ Ch,
           int N, int K, int mode,
           int zW, int zC, int zB)
{
    constexpr int WMW  = (BN == 128) ? 2 : 4;
    constexpr int WTM  = 128 / WMW;
    constexpr int MT   = WTM / 16;
    constexpr int ASZ  = 128 * PADK;
    constexpr int BSTR = BN + 8;
    constexpr int BSZ  = 64 * BSTR;
    constexpr int STG  = ASZ + BSZ;
    constexpr int CB   = BN / 8;

    extern __shared__ __half smem_dyn[];
    uint32_t smb = (uint32_t)__cvta_generic_to_shared(smem_dyn);

    int tid = threadIdx.x, wid = tid >> 5, lane = tid & 31;
    int n0 = blockIdx.x * BN, m0 = blockIdx.y * 128, z = blockIdx.z;
    B16  += (size_t)z * zW;
    bias += (size_t)z * zB;
    if (mode == 0 && Cf) Cf += (size_t)z * zC;
    if (mode == 2 && Ch) Ch += (size_t)z * zC;

    int wm = (wid % WMW) * WTM;
    int wn = (wid / WMW) * 32;

    float acc[MT][4][4];
#pragma unroll
    for (int mt = 0; mt < MT; mt++)
#pragma unroll
        for (int nt = 0; nt < 4; nt++)
#pragma unroll
            for (int f = 0; f < 4; f++) acc[mt][nt][f] = 0.f;

    auto load_stage = [&](int s, int k0) {
        uint32_t base = smb + (uint32_t)(s * STG) * 2;
#pragma unroll
        for (int i = 0; i < 4; i++) {
            int idx = tid + i * 256;
            int r = idx >> 3, ch = idx & 7;
            const char* g0 = (const char*)(A + (size_t)(m0 + r) * K + k0) + ch * 16;
            cpa16(base + (uint32_t)(r * PADK) * 2 + ch * 16, g0);
        }
#pragma unroll
        for (int i = 0; i < (64 * CB) / 256; i++) {
            int idx = tid + i * 256;
            int r = idx / CB, ch = idx % CB;
            const char* g0 = (const char*)(B16 + (size_t)(k0 + r) * N + n0) + ch * 16;
            cpa16(base + (uint32_t)(ASZ + r * BSTR) * 2 + ch * 16, g0);
        }
    };

    int nc = K / 64;
    load_stage(0, 0);
    CP_COMMIT();
    load_stage(1, 64);
    CP_COMMIT();

    uint32_t aRow  = (uint32_t)(wm + (lane & 15));
    uint32_t aK    = (uint32_t)((lane >> 4) * 8);
    uint32_t bkRow = (uint32_t)((lane & 7) + ((lane >> 3) & 1) * 8);
    uint32_t bkCol = (uint32_t)((lane >> 4) * 8);

    for (int c = 0; c < nc; c++) {
        int b = c % 3;
        if (c == nc - 1) { CP_WAIT0(); } else { CP_WAIT1(); }
        __syncthreads();
        if (c + 2 < nc) {
            load_stage((c + 2) % 3, (c + 2) * 64);
            CP_COMMIT();
        }

        uint32_t sbase = smb + (uint32_t)(b * STG) * 2;
#pragma unroll
        for (int k16 = 0; k16 < 4; k16++) {
            uint32_t bh[2][4];
#pragma unroll
            for (int np = 0; np < 2; np++) {
                uint32_t off = (uint32_t)(ASZ +
                    (k16 * 16 + bkRow) * BSTR + wn + np * 16 + bkCol) * 2;
                ldm_x4_t(bh[np], sbase + off);
            }
#pragma unroll
            for (int mt = 0; mt < MT; mt++) {
                uint32_t ah[4];
                uint32_t off = ((aRow + mt * 16) * PADK + (uint32_t)(k16 * 16) + aK) * 2;
                ldm_x4(ah, sbase + off);
#pragma unroll
                for (int nt = 0; nt < 4; nt++)
                    mma16816(acc[mt][nt], ah, &bh[nt >> 1][(nt & 1) * 2]);
            }
        }
    }

    int rbase = m0 + wm + (lane >> 2);
#pragma unroll
    for (int mt = 0; mt < MT; mt++) {
        int row = rbase + mt * 16;
#pragma unroll
        for (int nt = 0; nt < 4; nt++) {
            int col = n0 + wn + nt * 8 + (lane & 3) * 2;
            float b0 = bias[col], b1 = bias[col + 1];
            float v0 = acc[mt][nt][0] + b0;
            float v1 = acc[mt][nt][1] + b1;
            float v2 = acc[mt][nt][2] + b0;
            float v3 = acc[mt][nt][3] + b1;
            if (mode == 0) {
                *(float2*)(Cf + (size_t)row * N + col)       = make_float2(v0, v1);
                *(float2*)(Cf + (size_t)(row + 8) * N + col) = make_float2(v2, v3);
            } else {
                if (mode == 1) {
                    v0 = gelu_tanh(v0); v1 = gelu_tanh(v1);
                    v2 = gelu_tanh(v2); v3 = gelu_tanh(v3);
                }
                __half2 p0 = __halves2half2(__float2half(v0), __float2half(v1));
                __half2 p1 = __halves2half2(__float2half(v2), __float2half(v3));
                *(__half2*)(Ch + (size_t)row * N + col)       = p0;
                *(__half2*)(Ch + (size_t)(row + 8) * N + col) = p1;
            }
        }
    }
}

// ================= embed + LN (warp per token) =================
__global__ void embed_ln_kernel(const int* __restrict__ x,
                                const float* __restrict__ we,
                                const float* __restrict__ pe,
                                const float* __restrict__ te,
                                const float* __restrict__ lw,
                                const float* __restrict__ lb) {
    int t = blockIdx.x * 8 + (threadIdx.x >> 5);
    int lane = threadIdx.x & 31;
    int s = t % SS;
    int wid = x[t];
    size_t rb = (size_t)t * HH;

    float4 v[6];
    float sum = 0.f, sq = 0.f;
#pragma unroll
    for (int i = 0; i < 6; i++) {
        int c = (i * 32 + lane) * 4;
        float4 a = *(const float4*)&we[(size_t)wid * HH + c];
        float4 b = *(const float4*)&pe[s * HH + c];
        float4 e = *(const float4*)&te[c];
        v[i] = make_float4(a.x+b.x+e.x, a.y+b.y+e.y, a.z+b.z+e.z, a.w+b.w+e.w);
        sum += v[i].x + v[i].y + v[i].z + v[i].w;
        sq  += v[i].x*v[i].x + v[i].y*v[i].y + v[i].z*v[i].z + v[i].w*v[i].w;
    }
#pragma unroll
    for (int off = 16; off > 0; off >>= 1) {
        sum += __shfl_xor_sync(0xffffffffu, sum, off);
        sq  += __shfl_xor_sync(0xffffffffu, sq,  off);
    }
    float m = sum * (1.f/HH), var = sq * (1.f/HH) - m*m;
    float rstd = rsqrtf(var + 1e-12f);
#pragma unroll
    for (int i = 0; i < 6; i++) {
        int c = (i * 32 + lane) * 4;
        float4 w4 = *(const float4*)&lw[c];
        float4 b4 = *(const float4*)&lb[c];
        float o0 = (v[i].x-m)*rstd*w4.x + b4.x;
        float o1 = (v[i].y-m)*rstd*w4.y + b4.y;
        float o2 = (v[i].z-m)*rstd*w4.z + b4.z;
        float o3 = (v[i].w-m)*rstd*w4.w + b4.w;
        *(float4*)&g_h[rb + c] = make_float4(o0, o1, o2, o3);
        __half2 p0 = __halves2half2(__float2half(o0), __float2half(o1));
        __half2 p1 = __halves2half2(__float2half(o2), __float2half(o3));
        *(uint2*)(g_h16 + rb + c) = make_uint2(*(uint32_t*)&p0, *(uint32_t*)&p1);
    }
}

// ================= residual + LN (warp per token) =================
__global__ void resid_ln_kernel(const float* __restrict__ add,
                                const float* __restrict__ lw,
                                const float* __restrict__ lb) {
    int t = blockIdx.x * 8 + (threadIdx.x >> 5);
    int lane = threadIdx.x & 31;
    size_t rb = (size_t)t * HH;

    float4 v[6];
    float sum = 0.f, sq = 0.f;
#pragma unroll
    for (int i = 0; i < 6; i++) {
        int c = (i * 32 + lane) * 4;
        float4 a = *(const float4*)&g_h[rb + c];
        float4 b = *(const float4*)&add[rb + c];
        v[i] = make_float4(a.x+b.x, a.y+b.y, a.z+b.z, a.w+b.w);
        sum += v[i].x + v[i].y + v[i].z + v[i].w;
        sq  += v[i].x*v[i].x + v[i].y*v[i].y + v[i].z*v[i].z + v[i].w*v[i].w;
    }
#pragma unroll
    for (int off = 16; off > 0; off >>= 1) {
        sum += __shfl_xor_sync(0xffffffffu, sum, off);
        sq  += __shfl_xor_sync(0xffffffffu, sq,  off);
    }
    float m = sum * (1.f/HH), var = sq * (1.f/HH) - m*m;
    float rstd = rsqrtf(var + 1e-12f);
#pragma unroll
    for (int i = 0; i < 6; i++) {
        int c = (i * 32 + lane) * 4;
        float4 w4 = *(const float4*)&lw[c];
        float4 b4 = *(const float4*)&lb[c];
        float o0 = (v[i].x-m)*rstd*w4.x + b4.x;
        float o1 = (v[i].y-m)*rstd*w4.y + b4.y;
        float o2 = (v[i].z-m)*rstd*w4.z + b4.z;
        float o3 = (v[i].w-m)*rstd*w4.w + b4.w;
        *(float4*)&g_h[rb + c] = make_float4(o0, o1, o2, o3);
        __half2 p0 = __halves2half2(__float2half(o0), __float2half(o1));
        __half2 p1 = __halves2half2(__float2half(o2), __float2half(o3));
        *(uint2*)(g_h16 + rb + c) = make_uint2(*(uint32_t*)&p0, *(uint32_t*)&p1);
    }
}

// ================= attention v7: 64-q CTAs, 4 warps, 2 CTAs/SM =================
#define AQ_STR 72
#define AK_STR 72
#define AV_STR 72

__global__ __launch_bounds__(128, 2)
void attn_kernel_v7() {
    extern __shared__ __half smh[];
    __half* Qs = smh;                    // [64][72]
    __half* Ks = Qs + 64 * AQ_STR;       // [256][72]
    __half* Vs = Ks + 256 * AK_STR;      // [256][72]
    uint32_t sQ = (uint32_t)__cvta_generic_to_shared(Qs);
    uint32_t sK = (uint32_t)__cvta_generic_to_shared(Ks);
    uint32_t sV = (uint32_t)__cvta_generic_to_shared(Vs);

    const __half* gq = g_qkv16;
    const __half* gk = g_qkv16 + (size_t)TOK * HH;
    const __half* gv = g_qkv16 + 2 * (size_t)TOK * HH;

    int h = blockIdx.x, b = blockIdx.y, qh = blockIdx.z;
    int tid = threadIdx.x, lane = tid & 31, w = tid >> 5;
    size_t base = (size_t)(b * SS) * HH + h * DHH;
    int qoff = qh * 64;

    for (int i = tid; i < 64 * 8; i += 128) {
        int r = i >> 3, ch = i & 7;
        *(uint4*)&Qs[r * AQ_STR + ch * 8] =
            *(const uint4*)&gq[base + (size_t)(qoff + r) * HH + ch * 8];
    }
    for (int i = tid; i < 256 * 8; i += 128) {
        int r = i >> 3, ch = i & 7;
        size_t g = base + (size_t)r * HH + ch * 8;
        *(uint4*)&Ks[r * AK_STR + ch * 8] = *(const uint4*)&gk[g];
        *(uint4*)&Vs[r * AV_STR + ch * 8] = *(const uint4*)&gv[g];
    }
    __syncthreads();

    int wq = w * 16;   // warp's 16 query rows within the 64
    float c[16][2][4];
#pragma unroll
    for (int t = 0; t < 16; t++)
#pragma unroll
        for (int f = 0; f < 2; f++)
#pragma unroll
            for (int k = 0; k < 4; k++) c[t][f][k] = 0.f;

    uint32_t aRow = (uint32_t)(wq + (lane & 15));
    uint32_t aCol = (uint32_t)((lane >> 4) * 8);
    uint32_t bRow = (uint32_t)(((lane >> 4) & 1) * 8 + (lane & 7));
    uint32_t bCol = (uint32_t)(((lane >> 3) & 1) * 8);

#pragma unroll
    for (int k16 = 0; k16 < 4; k16++) {
        uint32_t aq[4];
        ldm_x4(aq, sQ + (aRow * AQ_STR + (uint32_t)(k16 * 16) + aCol) * 2);
#pragma unroll
        for (int t = 0; t < 16; t++) {
            uint32_t bk[4];
            ldm_x4(bk, sK + ((bRow + (uint32_t)(t * 16)) * AK_STR +
                             (uint32_t)(k16 * 16) + bCol) * 2);
            mma16816(c[t][0], aq, &bk[0]);
            mma16816(c[t][1], aq, &bk[2]);
        }
    }

    float m0 = -1e30f, m1 = -1e30f;
#pragma unroll
    for (int t = 0; t < 16; t++)
#pragma unroll
        for (int f = 0; f < 2; f++) {
            m0 = fmaxf(m0, fmaxf(c[t][f][0], c[t][f][1]));
            m1 = fmaxf(m1, fmaxf(c[t][f][2], c[t][f][3]));
        }
    m0 = fmaxf(m0, __shfl_xor_sync(0xffffffffu, m0, 1));
    m0 = fmaxf(m0, __shfl_xor_sync(0xffffffffu, m0, 2));
    m1 = fmaxf(m1, __shfl_xor_sync(0xffffffffu, m1, 1));
    m1 = fmaxf(m1, __shfl_xor_sync(0xffffffffu, m1, 2));

    float s0 = 0.f, s1 = 0.f;
#pragma unroll
    for (int t = 0; t < 16; t++)
#pragma unroll
        for (int f = 0; f < 2; f++) {
            c[t][f][0] = __expf(0.125f * (c[t][f][0] - m0));
            c[t][f][1] = __expf(0.125f * (c[t][f][1] - m0));
            c[t][f][2] = __expf(0.125f * (c[t][f][2] - m1));
            c[t][f][3] = __expf(0.125f * (c[t][f][3] - m1));
            s0 += c[t][f][0] + c[t][f][1];
            s1 += c[t][f][2] + c[t][f][3];
        }
    s0 += __shfl_xor_sync(0xffffffffu, s0, 1);
    s0 += __shfl_xor_sync(0xffffffffu, s0, 2);
    s1 += __shfl_xor_sync(0xffffffffu, s1, 1);
    s1 += __shfl_xor_sync(0xffffffffu, s1, 2);
    float iv0 = 1.f / s0, iv1 = 1.f / s1;

    float ctx[8][4];
#pragma unroll
    for (int nf = 0; nf < 8; nf++)
#pragma unroll
        for (int k = 0; k < 4; k++) ctx[nf][k] = 0.f;

    uint32_t vRow = (uint32_t)((lane & 7) + ((lane >> 3) & 1) * 8);
    uint32_t vCol = (uint32_t)((lane >> 4) * 8);

#pragma unroll
    for (int t = 0; t < 16; t++) {
        uint32_t pa[4];
        __half2 h0 = __halves2half2(__float2half(c[t][0][0] * iv0),
                                    __float2half(c[t][0][1] * iv0));
        __half2 h1 = __halves2half2(__float2half(c[t][0][2] * iv1),
                                    __float2half(c[t][0][3] * iv1));
        __half2 h2 = __halves2half2(__float2half(c[t][1][0] * iv0),
                                    __float2half(c[t][1][1] * iv0));
        __half2 h3 = __halves2half2(__float2half(c[t][1][2] * iv1),
                                    __float2half(c[t][1][3] * iv1));
        pa[0] = *(uint32_t*)&h0;
        pa[1] = *(uint32_t*)&h1;
        pa[2] = *(uint32_t*)&h2;
        pa[3] = *(uint32_t*)&h3;
#pragma unroll
        for (int dn = 0; dn < 4; dn++) {
            uint32_t bv[4];
            ldm_x4_t(bv, sV + ((vRow + (uint32_t)(t * 16)) * AV_STR +
                               (uint32_t)(dn * 16) + vCol) * 2);
            mma16816(ctx[dn * 2 + 0], pa, &bv[0]);
            mma16816(ctx[dn * 2 + 1], pa, &bv[2]);
        }
    }

    int q0 = qoff + wq + (lane >> 2);
#pragma unroll
    for (int nf = 0; nf < 8; nf++) {
        int d = nf * 8 + (lane & 3) * 2;
        size_t i0 = base + (size_t)q0 * HH + d;
        size_t i1 = base + (size_t)(q0 + 8) * HH + d;
        __half2 p0 = __halves2half2(__float2half(ctx[nf][0]), __float2half(ctx[nf][1]));
        __half2 p1 = __halves2half2(__float2half(ctx[nf][2]), __float2half(ctx[nf][3]));
        *(uint32_t*)(g_cx16 + i0) = *(uint32_t*)&p0;
        *(uint32_t*)(g_cx16 + i1) = *(uint32_t*)&p1;
    }
}

// ================= emissions (reads fp16 h) =================
__global__ void emissions_kernel(const float* __restrict__ cw,
                                 const float* __restrict__ cb) {
    int t = blockIdx.x, tid = threadIdx.x;
    float part[CC];
#pragma unroll
    for (int c = 0; c < CC; c++) part[c] = 0.f;
    for (int k = tid; k < HH; k += 256) {
        float hv = __half2float(g_h16[(size_t)t * HH + k]);
        const float* wr = cw + (size_t)k * CC;
#pragma unroll
        for (int c = 0; c < CC; c++) part[c] += hv * wr[c];
    }
#pragma unroll
    for (int c = 0; c < CC; c++)
        for (int off = 16; off > 0; off >>= 1)
            part[c] += __shfl_down_sync(0xffffffffu, part[c], off);

    __shared__ float wred[8][CC];
    int lane = tid & 31, w = tid >> 5;
    if (lane == 0)
#pragma unroll
        for (int c = 0; c < CC; c++) wred[w][c] = part[c];
    __syncthreads();
    if (tid < CC) {
        float s = cb[tid];
#pragma unroll
        for (int ww = 0; ww < 8; ww++) s += wred[ww][tid];
        g_em[(size_t)t * CC + tid] = s;
    }
}

// ================= CRF =================
__global__ void crf_kernel(const int* __restrict__ target,
                           const float* __restrict__ cstart,
                           const float* __restrict__ cend,
                           const float* __restrict__ ctrans,
                           float* __restrict__ out) {
    __shared__ float alpha[BB][CC];
    __shared__ float trans[CC][CC];
    __shared__ float den[BB], num[BB];
    int tid = threadIdx.x;

    if (tid < CC * CC) trans[tid / CC][tid % CC] = ctrans[tid];
    __syncthreads();

    int b = tid / CC, j = tid % CC;
    bool act = (tid < BB * CC);
    if (act) alpha[b][j] = cstart[j] + g_em[(size_t)(b * SS) * CC + j];
    __syncthreads();

    for (int s = 1; s < SS; s++) {
        float nv = 0.f;
        if (act) {
            float m = -1e30f;
#pragma unroll
            for (int i = 0; i < CC; i++) m = fmaxf(m, alpha[b][i] + trans[i][j]);
            float sum = 0.f;
#pragma unroll
            for (int i = 0; i < CC; i++) sum += __expf(alpha[b][i] + trans[i][j] - m);
            nv = m + __logf(sum) + g_em[(size_t)(b * SS + s) * CC + j];
            if (!(target[b * SS + s] > -1)) nv = alpha[b][j];
        }
        __syncthreads();
        if (act) alpha[b][j] = nv;
        __syncthreads();
    }

    if (act && j == 0) {
        float m = -1e30f;
#pragma unroll
        for (int jj = 0; jj < CC; jj++) m = fmaxf(m, alpha[b][jj] + cend[jj]);
        float sum = 0.f;
#pragma unroll
        for (int jj = 0; jj < CC; jj++) sum += __expf(alpha[b][jj] + cend[jj] - m);
        den[b] = m + __logf(sum);

        const int* tb = target + b * SS;
        int cnt = 0;
        for (int s = 0; s < SS; s++) cnt += (tb[s] > -1) ? 1 : 0;
        int send = cnt - 1;
        int t0 = tb[0] < 0 ? 0 : tb[0];
        float nu = cstart[t0] + g_em[(size_t)(b * SS) * CC + t0];
        for (int s = 1; s < SS; s++) {
            int ts = tb[s], tp = tb[s - 1];
            float mk = (ts > -1) ? 1.f : 0.f;
            int tsc = ts < 0 ? 0 : ts, tpc = tp < 0 ? 0 : tp;
            nu += mk * (trans[tpc][tsc] + g_em[(size_t)(b * SS + s) * CC + tsc]);
        }
        int last = tb[send < 0 ? 0 : send];
        nu += cend[last < 0 ? 0 : last];
        num[b] = nu;
    }
    __syncthreads();
    if (tid == 0) {
        float L = 0.f;
        for (int bb = 0; bb < BB; bb++) L += num[bb] - den[bb];
        out[0] = -L / BB;
    }
}

// ================= launch =================
extern "C" void kernel_launch(void* const* d_in, const int* in_sizes, int n_in,
                              void* d_out, int out_size) {
    const int*   x          = (const int*)  d_in[0];
    const int*   target     = (const int*)  d_in[1];
    const float* word_emb   = (const float*)d_in[2];
    const float* pos_emb    = (const float*)d_in[3];
    const float* type_emb   = (const float*)d_in[4];
    const float* emb_ln_w   = (const float*)d_in[5];
    const float* emb_ln_b   = (const float*)d_in[6];
    const float* qkv_w      = (const float*)d_in[7];
    const float* qkv_b      = (const float*)d_in[8];
    const float* attn_out_w = (const float*)d_in[9];
    const float* attn_out_b = (const float*)d_in[10];
    const float* attn_ln_w  = (const float*)d_in[11];
    const float* attn_ln_b  = (const float*)d_in[12];
    const float* ffn_w1     = (const float*)d_in[13];
    const float* ffn_b1     = (const float*)d_in[14];
    const float* ffn_w2     = (const float*)d_in[15];
    const float* ffn_b2     = (const float*)d_in[16];
    const float* ffn_ln_w   = (const float*)d_in[17];
    const float* ffn_ln_b   = (const float*)d_in[18];
    const float* cls_w      = (const float*)d_in[19];
    const float* cls_b      = (const float*)d_in[20];
    const float* crf_start  = (const float*)d_in[21];
    const float* crf_end    = (const float*)d_in[22];
    const float* crf_trans  = (const float*)d_in[23];
    float* out = (float*)d_out;

    float *pt1;
    __half *ph16, *pqkv16, *pcx16, *pf16;
    __half *pwq, *pwa, *pw1, *pw2;
    cudaGetSymbolAddress((void**)&pt1,    g_t1);
    cudaGetSymbolAddress((void**)&ph16,   g_h16);
    cudaGetSymbolAddress((void**)&pqkv16, g_qkv16);
    cudaGetSymbolAddress((void**)&pcx16,  g_cx16);
    cudaGetSymbolAddress((void**)&pf16,   g_f16);
    cudaGetSymbolAddress((void**)&pwq, w_qkv16);
    cudaGetSymbolAddress((void**)&pwa, w_ao16);
    cudaGetSymbolAddress((void**)&pw1, w_f116);
    cudaGetSymbolAddress((void**)&pw2, w_f216);

    const int SMEM_ATTN = (64*AQ_STR + 256*AK_STR + 256*AV_STR) * 2;     // 82944
    const int SMEM_G128 = 3 * (128*PADK + 64*(128+8)) * 2;               // 107520
    const int SMEM_G64  = 3 * (128*PADK + 64*(64+8)) * 2;                // 82944
    cudaFuncSetAttribute(attn_kernel_v7,
                         cudaFuncAttributeMaxDynamicSharedMemorySize, SMEM_ATTN);
    cudaFuncSetAttribute(k_mma<128>,
                         cudaFuncAttributeMaxDynamicSharedMemorySize, SMEM_G128);
    cudaFuncSetAttribute(k_mma<64>,
                         cudaFuncAttributeMaxDynamicSharedMemorySize, SMEM_G64);

    {
        size_t nq = (size_t)NLL*3*HH*HH;
        size_t na = (size_t)NLL*HH*HH;
        size_t n1 = (size_t)NLL*HH*FFF;
        size_t n2 = (size_t)NLL*FFF*HH;
        k_wconv<<<(unsigned)((nq/8 + 255)/256), 256>>>(qkv_w,      pwq, nq);
        k_wconv<<<(unsigned)((na/8 + 255)/256), 256>>>(attn_out_w, pwa, na);
        k_wconv<<<(unsigned)((n1/8 + 255)/256), 256>>>(ffn_w1,     pw1, n1);
        k_wconv<<<(unsigned)((n2/8 + 255)/256), 256>>>(ffn_w2,     pw2, n2);
    }

    embed_ln_kernel<<<TOK/8, 256>>>(x, word_emb, pos_emb, type_emb, emb_ln_w, emb_ln_b);

    dim3 gQKV(HH / 128, TOK / 128, 3);
    dim3 gH64(HH / 64,  TOK / 128, 1);
    dim3 gF  (FFF / 128, TOK / 128, 1);
    dim3 gA  (NHH, BB, 4);

    for (int l = 0; l < NLL; l++) {
        k_mma<128><<<gQKV, 256, SMEM_G128>>>(ph16,
            pwq + (size_t)l*3*HH*HH,
            qkv_b + (size_t)l*3*HH,
            nullptr, pqkv16,
            HH, HH, 2, HH*HH, TOK*HH, HH);

        attn_kernel_v7<<<gA, 128, SMEM_ATTN>>>();

        k_mma<64><<<gH64, 256, SMEM_G64>>>(pcx16,
            pwa + (size_t)l*HH*HH,
            attn_out_b + (size_t)l*HH,
            pt1, nullptr,
            HH, HH, 0, 0, 0, 0);
        resid_ln_kernel<<<TOK/8, 256>>>(pt1, attn_ln_w + (size_t)l*HH, attn_ln_b + (size_t)l*HH);

        k_mma<128><<<gF, 256, SMEM_G128>>>(ph16,
            pw1 + (size_t)l*HH*FFF,
            ffn_b1 + (size_t)l*FFF,
            nullptr, pf16,
            FFF, HH, 1, 0, 0, 0);

        k_mma<64><<<gH64, 256, SMEM_G64>>>(pf16,
            pw2 + (size_t)l*FFF*HH,
            ffn_b2 + (size_t)l*HH,
            pt1, nullptr,
            HH, FFF, 0, 0, 0, 0);
        resid_ln_kernel<<<TOK/8, 256>>>(pt1, ffn_ln_w + (size_t)l*HH, ffn_ln_b + (size_t)l*HH);
    }

    emissions_kernel<<<TOK, 256>>>(cls_w, cls_b);
    crf_kernel<<<1, 128>>>(target, crf_start, crf_end, crf_trans, out);
}